// round 10
// baseline (speedup 1.0000x reference)
#include <cuda_runtime.h>
#include <cuda_fp16.h>

#define NN 10000
#define NE 320000
#define NF4 (NN * 32)   // N * 128 floats / 4

// ---- device scratch ----
__device__ int            g_cnt[NN];
__device__ int            g_beg[NN];
__device__ int            g_total;
__device__ float          g_dinv[NN];
__device__ unsigned short g_rank[NE];   // rank of edge within its target bucket
__device__ int2           g_edge[NE];   // {src, wgt-as-int} packed
__device__ float4         g_curS[9][NF4]; // fp32 cur chain: slot 0 = x, 1..8 per-layer
__device__ uint2          g_curh[8][NF4]; // fp16 gather mirrors for slots 0..7
__device__ float          g_tk[8];
__device__ float          g_cst[1];

static __device__ __forceinline__ uint2 pack4h(float a, float b, float c, float d) {
    __half2 lo = __floats2half2_rn(a, b);
    __half2 hi = __floats2half2_rn(c, d);
    uint2 r;
    r.x = *reinterpret_cast<unsigned*>(&lo);
    r.y = *reinterpret_cast<unsigned*>(&hi);
    return r;
}

// ---- init: slot0 = x (fp32 + fp16 mirror), counters = 0 ----
__global__ void k_init(const float4* __restrict__ x4) {
    int i = blockIdx.x * blockDim.x + threadIdx.x;
    if (i < NF4) {
        float4 v = x4[i];
        g_curS[0][i] = v;
        g_curh[0][i] = pack4h(v.x, v.y, v.z, v.w);
    }
    if (i < NN) g_cnt[i] = 0;
    if (i == 0) g_total = 0;
}

// ---- count + rank: atomic return value IS the within-bucket rank ----
__global__ void k_count(const int* __restrict__ ei) {
    int e = blockIdx.x * blockDim.x + threadIdx.x;
    if (e < NE) {
        int rank = atomicAdd(&g_cnt[ei[NE + e]], 1);
        g_rank[e] = (unsigned short)rank;
    }
}

// ---- dinv = deg^-1/2 (0 -> 1); bucket allocation; scalar prep ----
__global__ void k_dinv(const float* __restrict__ kv, const float* __restrict__ wt) {
    int n = blockIdx.x * blockDim.x + threadIdx.x;
    if (n < NN) {
        int c = g_cnt[n];
        g_dinv[n] = rsqrtf((float)(c ? c : 1));
        g_beg[n] = atomicAdd(&g_total, c);
    }
    if (n < 8)  g_tk[n] = tanhf(kv[n]);
    if (n == 8) g_cst[0] = 1.f / (1.f + expf(-wt[0]));
}

// ---- fill buckets: ATOMIC-FREE (beg + precomputed rank) ----
__global__ void k_fill(const int* __restrict__ ei) {
    int e = blockIdx.x * blockDim.x + threadIdx.x;
    if (e < NE) {
        int r = ei[e];
        int c = ei[NE + e];
        int pos = g_beg[c] + (int)g_rank[e];
        float w = g_dinv[r] * g_dinv[c];
        g_edge[pos] = make_int2(r, __float_as_int(w));
    }
}

// ---- one propagation layer: warp-per-node, fp16 gather, unroll x8 ----
__global__ void __launch_bounds__(256) k_layer(int s) {
    int gw   = (blockIdx.x * blockDim.x + threadIdx.x) >> 5;
    int lane = threadIdx.x & 31;
    if (gw >= NN) return;
    const uint2*  __restrict__ hin  = g_curh[s];
    const float4* __restrict__ cin  = g_curS[s];
    float4* __restrict__       cout = g_curS[s + 1];

    int beg = g_beg[gw];
    int end = beg + g_cnt[gw];
    float ax = 0.f, ay = 0.f, az = 0.f, aw = 0.f;

    int e = beg;
    for (; e + 7 < end; e += 8) {
        int2 e0 = g_edge[e + 0], e1 = g_edge[e + 1], e2 = g_edge[e + 2], e3 = g_edge[e + 3];
        int2 e4 = g_edge[e + 4], e5 = g_edge[e + 5], e6 = g_edge[e + 6], e7 = g_edge[e + 7];
        uint2 p0 = hin[e0.x * 32 + lane];
        uint2 p1 = hin[e1.x * 32 + lane];
        uint2 p2 = hin[e2.x * 32 + lane];
        uint2 p3 = hin[e3.x * 32 + lane];
        uint2 p4 = hin[e4.x * 32 + lane];
        uint2 p5 = hin[e5.x * 32 + lane];
        uint2 p6 = hin[e6.x * 32 + lane];
        uint2 p7 = hin[e7.x * 32 + lane];
#define ACC(P, EV) do {                                                   \
        float w = __int_as_float((EV).y);                                 \
        float2 lo = __half22float2(*reinterpret_cast<__half2*>(&(P).x));  \
        float2 hi = __half22float2(*reinterpret_cast<__half2*>(&(P).y));  \
        ax = fmaf(w, lo.x, ax); ay = fmaf(w, lo.y, ay);                   \
        az = fmaf(w, hi.x, az); aw = fmaf(w, hi.y, aw); } while (0)
        ACC(p0, e0); ACC(p1, e1); ACC(p2, e2); ACC(p3, e3);
        ACC(p4, e4); ACC(p5, e5); ACC(p6, e6); ACC(p7, e7);
    }
    for (; e + 3 < end; e += 4) {
        int2 e0 = g_edge[e + 0], e1 = g_edge[e + 1], e2 = g_edge[e + 2], e3 = g_edge[e + 3];
        uint2 p0 = hin[e0.x * 32 + lane];
        uint2 p1 = hin[e1.x * 32 + lane];
        uint2 p2 = hin[e2.x * 32 + lane];
        uint2 p3 = hin[e3.x * 32 + lane];
        ACC(p0, e0); ACC(p1, e1); ACC(p2, e2); ACC(p3, e3);
    }
    for (; e < end; e++) {
        int2 ev = g_edge[e];
        uint2 p = hin[ev.x * 32 + lane];
        ACC(p, ev);
    }
#undef ACC

    int off = gw * 32 + lane;
    float4 cv = cin[off];   // fp32 carry
    float4 o = make_float4(cv.x - ax, cv.y - ay, cv.z - az, cv.w - aw);
    cout[off] = o;
    if (s + 1 < 8) g_curh[s + 1][off] = pack4h(o.x, o.y, o.z, o.w);
}

// ---- epilogue: u = sum tk_i*cur_{i+1}; h = c*u+(1-c)*x; relu(h@W^T+b) ----
// BM=64, BN=128 (full width, single column block: curS read exactly once),
// BK=32, 4x8 register tile, 256 threads.
__global__ void __launch_bounds__(256) k_out(const float4* __restrict__ x4,
                                             const float4* __restrict__ W4,
                                             const float*  __restrict__ bias,
                                             float*        __restrict__ out) {
    __shared__ float sA[32][68];    // [k][m]
    __shared__ float sB[32][132];   // [k][j], row padded to 132 (float4-aligned)
    int mblk = blockIdx.x * 64;
    int tid = threadIdx.x;
    int tx = tid & 15, ty = tid >> 4;

    float c = g_cst[0], d = 1.f - c;
    float tk[8];
#pragma unroll
    for (int i = 0; i < 8; i++) tk[i] = g_tk[i];

    float acc[4][8];
#pragma unroll
    for (int i = 0; i < 4; i++)
#pragma unroll
        for (int j = 0; j < 8; j++) acc[i][j] = 0.f;

    for (int k0 = 0; k0 < 128; k0 += 32) {
        // sA: 64 rows x 32 k = 512 float4-groups, 2 per thread
#pragma unroll
        for (int l = 0; l < 2; l++) {
            int idx = tid + l * 256;
            int m  = idx >> 3;
            int kq = idx & 7;
            int kk = kq * 4;
            int node = mblk + m;
            float ux = 0.f, uy = 0.f, uz = 0.f, uw = 0.f;
            float4 xv = make_float4(0.f, 0.f, 0.f, 0.f);
            if (node < NN) {
                int off = node * 32 + (k0 >> 2) + kq;
                xv = x4[off];
#pragma unroll
                for (int i = 0; i < 8; i++) {
                    float4 cv = g_curS[i + 1][off];
                    ux = fmaf(tk[i], cv.x, ux); uy = fmaf(tk[i], cv.y, uy);
                    uz = fmaf(tk[i], cv.z, uz); uw = fmaf(tk[i], cv.w, uw);
                }
            }
            sA[kk + 0][m] = c * ux + d * xv.x;
            sA[kk + 1][m] = c * uy + d * xv.y;
            sA[kk + 2][m] = c * uz + d * xv.z;
            sA[kk + 3][m] = c * uw + d * xv.w;
        }
        // sB: 128 rows(j) x 32 k = 1024 float4-groups, 4 per thread
#pragma unroll
        for (int l = 0; l < 4; l++) {
            int idx = tid + l * 256;
            int j  = idx >> 3;
            int kq = idx & 7;
            int kk = kq * 4;
            float4 wv = W4[j * 32 + (k0 >> 2) + kq];
            sB[kk + 0][j] = wv.x;
            sB[kk + 1][j] = wv.y;
            sB[kk + 2][j] = wv.z;
            sB[kk + 3][j] = wv.w;
        }
        __syncthreads();
#pragma unroll
        for (int kk = 0; kk < 32; kk++) {
            float a[4];
#pragma unroll
            for (int i = 0; i < 4; i++) a[i] = sA[kk][ty * 4 + i];
            float4 b0 = *reinterpret_cast<const float4*>(&sB[kk][tx * 8]);
            float4 b1 = *reinterpret_cast<const float4*>(&sB[kk][tx * 8 + 4]);
            float bb[8] = {b0.x, b0.y, b0.z, b0.w, b1.x, b1.y, b1.z, b1.w};
#pragma unroll
            for (int i = 0; i < 4; i++)
#pragma unroll
                for (int j = 0; j < 8; j++)
                    acc[i][j] = fmaf(a[i], bb[j], acc[i][j]);
        }
        __syncthreads();
    }

#pragma unroll
    for (int i = 0; i < 4; i++) {
        int node = mblk + ty * 4 + i;
        if (node >= NN) continue;
#pragma unroll
        for (int j = 0; j < 8; j++) {
            int jj = tx * 8 + j;
            float v = acc[i][j] + bias[jj];
            out[node * 128 + jj] = v > 0.f ? v : 0.f;
        }
    }
}

extern "C" void kernel_launch(void* const* d_in, const int* in_sizes, int n_in,
                              void* d_out, int out_size) {
    const float4* x4   = (const float4*)d_in[0];
    const int*    ei   = (const int*)d_in[1];
    const float*  kv   = (const float*)d_in[2];
    const float*  wt   = (const float*)d_in[3];
    const float4* W4   = (const float4*)d_in[4];
    const float*  bias = (const float*)d_in[5];
    float*        out  = (float*)d_out;

    k_init<<<(NF4 + 255) / 256, 256>>>(x4);
    k_count<<<(NE + 255) / 256, 256>>>(ei);
    k_dinv<<<(NN + 255) / 256, 256>>>(kv, wt);
    k_fill<<<(NE + 255) / 256, 256>>>(ei);

    for (int l = 0; l < 8; l++)
        k_layer<<<(NN * 32 + 255) / 256, 256>>>(l);

    k_out<<<(NN + 63) / 64, 256>>>(x4, W4, bias, out);
}

// round 15
// speedup vs baseline: 1.1161x; 1.1161x over previous
#include <cuda_runtime.h>
#include <cuda_fp16.h>

#define NN 10000
#define NE 320000
#define NF4 (NN * 32)   // N * 128 floats / 4

// ---- device scratch ----
__device__ int            g_cnt[NN];
__device__ int            g_beg[NN];
__device__ int            g_total;
__device__ float          g_dinv[NN];
__device__ unsigned short g_rank[NE];   // rank of edge within its target bucket
__device__ int2           g_edge[NE];   // {src, wgt-as-int} packed
__device__ float4         g_curS[9][NF4]; // fp32 cur chain: slot 0 = x, 1..8 per-layer
__device__ uint2          g_curh[8][NF4]; // fp16 gather mirrors for slots 0..7
__device__ float          g_tk[8];
__device__ float          g_cst[1];

static __device__ __forceinline__ uint2 pack4h(float a, float b, float c, float d) {
    __half2 lo = __floats2half2_rn(a, b);
    __half2 hi = __floats2half2_rn(c, d);
    uint2 r;
    r.x = *reinterpret_cast<unsigned*>(&lo);
    r.y = *reinterpret_cast<unsigned*>(&hi);
    return r;
}

// ---- init: slot0 = x (fp32 + fp16 mirror), counters = 0 ----
__global__ void k_init(const float4* __restrict__ x4) {
    int i = blockIdx.x * blockDim.x + threadIdx.x;
    if (i < NF4) {
        float4 v = x4[i];
        g_curS[0][i] = v;
        g_curh[0][i] = pack4h(v.x, v.y, v.z, v.w);
    }
    if (i < NN) g_cnt[i] = 0;
    if (i == 0) g_total = 0;
}

// ---- count + rank: atomic return value IS the within-bucket rank ----
__global__ void k_count(const int* __restrict__ ei) {
    int e = blockIdx.x * blockDim.x + threadIdx.x;
    if (e < NE) {
        int rank = atomicAdd(&g_cnt[ei[NE + e]], 1);
        g_rank[e] = (unsigned short)rank;
    }
}

// ---- dinv = deg^-1/2 (0 -> 1); bucket allocation; scalar prep ----
__global__ void k_dinv(const float* __restrict__ kv, const float* __restrict__ wt) {
    int n = blockIdx.x * blockDim.x + threadIdx.x;
    if (n < NN) {
        int c = g_cnt[n];
        g_dinv[n] = rsqrtf((float)(c ? c : 1));
        g_beg[n] = atomicAdd(&g_total, c);
    }
    if (n < 8)  g_tk[n] = tanhf(kv[n]);
    if (n == 8) g_cst[0] = 1.f / (1.f + expf(-wt[0]));
}

// ---- fill buckets: ATOMIC-FREE (beg + precomputed rank) ----
__global__ void k_fill(const int* __restrict__ ei) {
    int e = blockIdx.x * blockDim.x + threadIdx.x;
    if (e < NE) {
        int r = ei[e];
        int c = ei[NE + e];
        int pos = g_beg[c] + (int)g_rank[e];
        float w = g_dinv[r] * g_dinv[c];
        g_edge[pos] = make_int2(r, __float_as_int(w));
    }
}

// ---- one propagation layer: warp-per-node, fp16 gather, unroll x8 ----
__global__ void __launch_bounds__(256) k_layer(int s) {
    int gw   = (blockIdx.x * blockDim.x + threadIdx.x) >> 5;
    int lane = threadIdx.x & 31;
    if (gw >= NN) return;
    const uint2*  __restrict__ hin  = g_curh[s];
    const float4* __restrict__ cin  = g_curS[s];
    float4* __restrict__       cout = g_curS[s + 1];

    int beg = g_beg[gw];
    int end = beg + g_cnt[gw];
    float ax = 0.f, ay = 0.f, az = 0.f, aw = 0.f;

    int e = beg;
    for (; e + 7 < end; e += 8) {
        int2 e0 = g_edge[e + 0], e1 = g_edge[e + 1], e2 = g_edge[e + 2], e3 = g_edge[e + 3];
        int2 e4 = g_edge[e + 4], e5 = g_edge[e + 5], e6 = g_edge[e + 6], e7 = g_edge[e + 7];
        uint2 p0 = hin[e0.x * 32 + lane];
        uint2 p1 = hin[e1.x * 32 + lane];
        uint2 p2 = hin[e2.x * 32 + lane];
        uint2 p3 = hin[e3.x * 32 + lane];
        uint2 p4 = hin[e4.x * 32 + lane];
        uint2 p5 = hin[e5.x * 32 + lane];
        uint2 p6 = hin[e6.x * 32 + lane];
        uint2 p7 = hin[e7.x * 32 + lane];
#define ACC(P, EV) do {                                                   \
        float w = __int_as_float((EV).y);                                 \
        float2 lo = __half22float2(*reinterpret_cast<__half2*>(&(P).x));  \
        float2 hi = __half22float2(*reinterpret_cast<__half2*>(&(P).y));  \
        ax = fmaf(w, lo.x, ax); ay = fmaf(w, lo.y, ay);                   \
        az = fmaf(w, hi.x, az); aw = fmaf(w, hi.y, aw); } while (0)
        ACC(p0, e0); ACC(p1, e1); ACC(p2, e2); ACC(p3, e3);
        ACC(p4, e4); ACC(p5, e5); ACC(p6, e6); ACC(p7, e7);
    }
    for (; e + 3 < end; e += 4) {
        int2 e0 = g_edge[e + 0], e1 = g_edge[e + 1], e2 = g_edge[e + 2], e3 = g_edge[e + 3];
        uint2 p0 = hin[e0.x * 32 + lane];
        uint2 p1 = hin[e1.x * 32 + lane];
        uint2 p2 = hin[e2.x * 32 + lane];
        uint2 p3 = hin[e3.x * 32 + lane];
        ACC(p0, e0); ACC(p1, e1); ACC(p2, e2); ACC(p3, e3);
    }
    for (; e < end; e++) {
        int2 ev = g_edge[e];
        uint2 p = hin[ev.x * 32 + lane];
        ACC(p, ev);
    }
#undef ACC

    int off = gw * 32 + lane;
    float4 cv = cin[off];   // fp32 carry
    float4 o = make_float4(cv.x - ax, cv.y - ay, cv.z - az, cv.w - aw);
    cout[off] = o;
    if (s + 1 < 8) g_curh[s + 1][off] = pack4h(o.x, o.y, o.z, o.w);
}

// ---- epilogue (R9 version): u = sum tk_i*cur_{i+1}; h = c*u+(1-c)*x;
// relu(h@W^T+b). BM=64, BN=64 (grid.y=2), BK=32, 4x4 register tile.
__global__ void __launch_bounds__(256) k_out(const float4* __restrict__ x4,
                                             const float4* __restrict__ W4,
                                             const float*  __restrict__ bias,
                                             float*        __restrict__ out) {
    __shared__ float sA[32][68];
    __shared__ float sB[32][68];
    int mblk = blockIdx.x * 64;
    int nblk = blockIdx.y * 64;
    int tid = threadIdx.x;
    int tx = tid & 15, ty = tid >> 4;

    float c = g_cst[0], d = 1.f - c;
    float tk[8];
#pragma unroll
    for (int i = 0; i < 8; i++) tk[i] = g_tk[i];

    float acc[4][4];
#pragma unroll
    for (int i = 0; i < 4; i++)
#pragma unroll
        for (int j = 0; j < 4; j++) acc[i][j] = 0.f;

    for (int k0 = 0; k0 < 128; k0 += 32) {
#pragma unroll
        for (int l = 0; l < 2; l++) {
            int idx = tid + l * 256;
            int m  = idx >> 3;
            int kq = idx & 7;
            int kk = kq * 4;
            int node = mblk + m;
            float ux = 0.f, uy = 0.f, uz = 0.f, uw = 0.f;
            float4 xv = make_float4(0.f, 0.f, 0.f, 0.f);
            if (node < NN) {
                int off = node * 32 + (k0 >> 2) + kq;
                xv = x4[off];
#pragma unroll
                for (int i = 0; i < 8; i++) {
                    float4 cv = g_curS[i + 1][off];
                    ux = fmaf(tk[i], cv.x, ux); uy = fmaf(tk[i], cv.y, uy);
                    uz = fmaf(tk[i], cv.z, uz); uw = fmaf(tk[i], cv.w, uw);
                }
            }
            sA[kk + 0][m] = c * ux + d * xv.x;
            sA[kk + 1][m] = c * uy + d * xv.y;
            sA[kk + 2][m] = c * uz + d * xv.z;
            sA[kk + 3][m] = c * uw + d * xv.w;
            float4 wv = W4[(nblk + m) * 32 + (k0 >> 2) + kq];
            sB[kk + 0][m] = wv.x;
            sB[kk + 1][m] = wv.y;
            sB[kk + 2][m] = wv.z;
            sB[kk + 3][m] = wv.w;
        }
        __syncthreads();
#pragma unroll
        for (int kk = 0; kk < 32; kk++) {
            float a[4], bb[4];
#pragma unroll
            for (int i = 0; i < 4; i++) a[i] = sA[kk][ty * 4 + i];
#pragma unroll
            for (int j = 0; j < 4; j++) bb[j] = sB[kk][tx * 4 + j];
#pragma unroll
            for (int i = 0; i < 4; i++)
#pragma unroll
                for (int j = 0; j < 4; j++)
                    acc[i][j] = fmaf(a[i], bb[j], acc[i][j]);
        }
        __syncthreads();
    }

#pragma unroll
    for (int i = 0; i < 4; i++) {
        int node = mblk + ty * 4 + i;
        if (node >= NN) continue;
#pragma unroll
        for (int j = 0; j < 4; j++) {
            int jj = nblk + tx * 4 + j;
            float v = acc[i][j] + bias[jj];
            out[node * 128 + jj] = v > 0.f ? v : 0.f;
        }
    }
}

extern "C" void kernel_launch(void* const* d_in, const int* in_sizes, int n_in,
                              void* d_out, int out_size) {
    const float4* x4   = (const float4*)d_in[0];
    const int*    ei   = (const int*)d_in[1];
    const float*  kv   = (const float*)d_in[2];
    const float*  wt   = (const float*)d_in[3];
    const float4* W4   = (const float4*)d_in[4];
    const float*  bias = (const float*)d_in[5];
    float*        out  = (float*)d_out;

    k_init<<<(NF4 + 255) / 256, 256>>>(x4);
    k_count<<<(NE + 255) / 256, 256>>>(ei);
    k_dinv<<<(NN + 255) / 256, 256>>>(kv, wt);
    k_fill<<<(NE + 255) / 256, 256>>>(ei);

    for (int l = 0; l < 8; l++)
        k_layer<<<(NN * 32 + 255) / 256, 256>>>(l);

    dim3 g((NN + 63) / 64, 2);
    k_out<<<g, 256>>>(x4, W4, bias, out);
}

// round 16
// speedup vs baseline: 1.1180x; 1.0017x over previous
#include <cuda_runtime.h>
#include <cuda_fp16.h>

#define NN 10000
#define NE 320000
#define NF4 (NN * 32)   // N * 128 floats / 4

// ---- device scratch ----
__device__ int            g_cnt[NN];
__device__ int            g_beg[NN];
__device__ int            g_total;
__device__ float          g_dinv[NN];
__device__ unsigned short g_rank[NE];   // rank of edge within its target bucket
__device__ int2           g_edge[NE];   // {src, wgt-as-int} packed
__device__ float4         g_curS[9][NF4]; // fp32 cur chain: slot 0 = x, 1..8 per-layer
__device__ uint2          g_curh[8][NF4]; // fp16 gather mirrors for slots 0..7
__device__ float4         g_h[NF4];       // blended h = c*u + (1-c)*x
__device__ float          g_tk[8];
__device__ float          g_cst[1];

static __device__ __forceinline__ uint2 pack4h(float a, float b, float c, float d) {
    __half2 lo = __floats2half2_rn(a, b);
    __half2 hi = __floats2half2_rn(c, d);
    uint2 r;
    r.x = *reinterpret_cast<unsigned*>(&lo);
    r.y = *reinterpret_cast<unsigned*>(&hi);
    return r;
}

// ---- init: slot0 = x (fp32 + fp16 mirror), counters = 0 ----
__global__ void k_init(const float4* __restrict__ x4) {
    int i = blockIdx.x * blockDim.x + threadIdx.x;
    if (i < NF4) {
        float4 v = x4[i];
        g_curS[0][i] = v;
        g_curh[0][i] = pack4h(v.x, v.y, v.z, v.w);
    }
    if (i < NN) g_cnt[i] = 0;
    if (i == 0) g_total = 0;
}

// ---- count + rank: atomic return value IS the within-bucket rank ----
__global__ void k_count(const int* __restrict__ ei) {
    int e = blockIdx.x * blockDim.x + threadIdx.x;
    if (e < NE) {
        int rank = atomicAdd(&g_cnt[ei[NE + e]], 1);
        g_rank[e] = (unsigned short)rank;
    }
}

// ---- dinv = deg^-1/2 (0 -> 1); bucket allocation; scalar prep ----
__global__ void k_dinv(const float* __restrict__ kv, const float* __restrict__ wt) {
    int n = blockIdx.x * blockDim.x + threadIdx.x;
    if (n < NN) {
        int c = g_cnt[n];
        g_dinv[n] = rsqrtf((float)(c ? c : 1));
        g_beg[n] = atomicAdd(&g_total, c);
    }
    if (n < 8)  g_tk[n] = tanhf(kv[n]);
    if (n == 8) g_cst[0] = 1.f / (1.f + expf(-wt[0]));
}

// ---- fill buckets: ATOMIC-FREE (beg + precomputed rank) ----
__global__ void k_fill(const int* __restrict__ ei) {
    int e = blockIdx.x * blockDim.x + threadIdx.x;
    if (e < NE) {
        int r = ei[e];
        int c = ei[NE + e];
        int pos = g_beg[c] + (int)g_rank[e];
        float w = g_dinv[r] * g_dinv[c];
        g_edge[pos] = make_int2(r, __float_as_int(w));
    }
}

// ---- one propagation layer: warp-per-node, fp16 gather, unroll x8 ----
__global__ void __launch_bounds__(256) k_layer(int s) {
    int gw   = (blockIdx.x * blockDim.x + threadIdx.x) >> 5;
    int lane = threadIdx.x & 31;
    if (gw >= NN) return;
    const uint2*  __restrict__ hin  = g_curh[s];
    const float4* __restrict__ cin  = g_curS[s];
    float4* __restrict__       cout = g_curS[s + 1];

    int beg = g_beg[gw];
    int end = beg + g_cnt[gw];
    float ax = 0.f, ay = 0.f, az = 0.f, aw = 0.f;

    int e = beg;
    for (; e + 7 < end; e += 8) {
        int2 e0 = g_edge[e + 0], e1 = g_edge[e + 1], e2 = g_edge[e + 2], e3 = g_edge[e + 3];
        int2 e4 = g_edge[e + 4], e5 = g_edge[e + 5], e6 = g_edge[e + 6], e7 = g_edge[e + 7];
        uint2 p0 = hin[e0.x * 32 + lane];
        uint2 p1 = hin[e1.x * 32 + lane];
        uint2 p2 = hin[e2.x * 32 + lane];
        uint2 p3 = hin[e3.x * 32 + lane];
        uint2 p4 = hin[e4.x * 32 + lane];
        uint2 p5 = hin[e5.x * 32 + lane];
        uint2 p6 = hin[e6.x * 32 + lane];
        uint2 p7 = hin[e7.x * 32 + lane];
#define ACC(P, EV) do {                                                   \
        float w = __int_as_float((EV).y);                                 \
        float2 lo = __half22float2(*reinterpret_cast<__half2*>(&(P).x));  \
        float2 hi = __half22float2(*reinterpret_cast<__half2*>(&(P).y));  \
        ax = fmaf(w, lo.x, ax); ay = fmaf(w, lo.y, ay);                   \
        az = fmaf(w, hi.x, az); aw = fmaf(w, hi.y, aw); } while (0)
        ACC(p0, e0); ACC(p1, e1); ACC(p2, e2); ACC(p3, e3);
        ACC(p4, e4); ACC(p5, e5); ACC(p6, e6); ACC(p7, e7);
    }
    for (; e + 3 < end; e += 4) {
        int2 e0 = g_edge[e + 0], e1 = g_edge[e + 1], e2 = g_edge[e + 2], e3 = g_edge[e + 3];
        uint2 p0 = hin[e0.x * 32 + lane];
        uint2 p1 = hin[e1.x * 32 + lane];
        uint2 p2 = hin[e2.x * 32 + lane];
        uint2 p3 = hin[e3.x * 32 + lane];
        ACC(p0, e0); ACC(p1, e1); ACC(p2, e2); ACC(p3, e3);
    }
    for (; e < end; e++) {
        int2 ev = g_edge[e];
        uint2 p = hin[ev.x * 32 + lane];
        ACC(p, ev);
    }
#undef ACC

    int off = gw * 32 + lane;
    float4 cv = cin[off];   // fp32 carry
    float4 o = make_float4(cv.x - ax, cv.y - ay, cv.z - az, cv.w - aw);
    cout[off] = o;
    if (s + 1 < 8) g_curh[s + 1][off] = pack4h(o.x, o.y, o.z, o.w);
}

// ---- blend: h = c * sum tk_i*cur_{i+1} + (1-c)*x  (pure coalesced stream) ----
__global__ void __launch_bounds__(256) k_blend(const float4* __restrict__ x4) {
    int i = blockIdx.x * blockDim.x + threadIdx.x;
    if (i >= NF4) return;
    float c = g_cst[0], d = 1.f - c;
    float ux = 0.f, uy = 0.f, uz = 0.f, uw = 0.f;
#pragma unroll
    for (int s = 0; s < 8; s++) {
        float tk = g_tk[s];
        float4 cv = g_curS[s + 1][i];
        ux = fmaf(tk, cv.x, ux); uy = fmaf(tk, cv.y, uy);
        uz = fmaf(tk, cv.z, uz); uw = fmaf(tk, cv.w, uw);
    }
    float4 xv = x4[i];
    g_h[i] = make_float4(c * ux + d * xv.x, c * uy + d * xv.y,
                         c * uz + d * xv.z, c * uw + d * xv.w);
}

// ---- epilogue: pure GEMM out = relu(h @ W^T + b) ----
// BM=64, BN=64 (grid.y=2), BK=32, 4x4 register tile (R9-proven schedule).
__global__ void __launch_bounds__(256) k_out(const float4* __restrict__ W4,
                                             const float*  __restrict__ bias,
                                             float*        __restrict__ out) {
    __shared__ float sA[32][68];
    __shared__ float sB[32][68];
    int mblk = blockIdx.x * 64;
    int nblk = blockIdx.y * 64;
    int tid = threadIdx.x;
    int tx = tid & 15, ty = tid >> 4;

    float acc[4][4];
#pragma unroll
    for (int i = 0; i < 4; i++)
#pragma unroll
        for (int j = 0; j < 4; j++) acc[i][j] = 0.f;

    for (int k0 = 0; k0 < 128; k0 += 32) {
#pragma unroll
        for (int l = 0; l < 2; l++) {
            int idx = tid + l * 256;
            int m  = idx >> 3;
            int kq = idx & 7;
            int kk = kq * 4;
            int node = mblk + m;
            float4 hv = make_float4(0.f, 0.f, 0.f, 0.f);
            if (node < NN) hv = g_h[node * 32 + (k0 >> 2) + kq];
            sA[kk + 0][m] = hv.x;
            sA[kk + 1][m] = hv.y;
            sA[kk + 2][m] = hv.z;
            sA[kk + 3][m] = hv.w;
            float4 wv = W4[(nblk + m) * 32 + (k0 >> 2) + kq];
            sB[kk + 0][m] = wv.x;
            sB[kk + 1][m] = wv.y;
            sB[kk + 2][m] = wv.z;
            sB[kk + 3][m] = wv.w;
        }
        __syncthreads();
#pragma unroll
        for (int kk = 0; kk < 32; kk++) {
            float a[4], bb[4];
#pragma unroll
            for (int i = 0; i < 4; i++) a[i] = sA[kk][ty * 4 + i];
#pragma unroll
            for (int j = 0; j < 4; j++) bb[j] = sB[kk][tx * 4 + j];
#pragma unroll
            for (int i = 0; i < 4; i++)
#pragma unroll
                for (int j = 0; j < 4; j++)
                    acc[i][j] = fmaf(a[i], bb[j], acc[i][j]);
        }
        __syncthreads();
    }

#pragma unroll
    for (int i = 0; i < 4; i++) {
        int node = mblk + ty * 4 + i;
        if (node >= NN) continue;
#pragma unroll
        for (int j = 0; j < 4; j++) {
            int jj = nblk + tx * 4 + j;
            float v = acc[i][j] + bias[jj];
            out[node * 128 + jj] = v > 0.f ? v : 0.f;
        }
    }
}

extern "C" void kernel_launch(void* const* d_in, const int* in_sizes, int n_in,
                              void* d_out, int out_size) {
    const float4* x4   = (const float4*)d_in[0];
    const int*    ei   = (const int*)d_in[1];
    const float*  kv   = (const float*)d_in[2];
    const float*  wt   = (const float*)d_in[3];
    const float4* W4   = (const float4*)d_in[4];
    const float*  bias = (const float*)d_in[5];
    float*        out  = (float*)d_out;

    k_init<<<(NF4 + 255) / 256, 256>>>(x4);
    k_count<<<(NE + 255) / 256, 256>>>(ei);
    k_dinv<<<(NN + 255) / 256, 256>>>(kv, wt);
    k_fill<<<(NE + 255) / 256, 256>>>(ei);

    for (int l = 0; l < 8; l++)
        k_layer<<<(NN * 32 + 255) / 256, 256>>>(l);

    k_blend<<<(NF4 + 255) / 256, 256>>>(x4);

    dim3 g((NN + 63) / 64, 2);
    k_out<<<g, 256>>>(W4, bias, out);
}

// round 17
// speedup vs baseline: 1.1959x; 1.0697x over previous
#include <cuda_runtime.h>
#include <cuda_fp16.h>

#define NN 10000
#define NE 320000
#define NF4 (NN * 32)   // N * 128 floats / 4 (one uint2 = 4 halves per slot)

// ---- device scratch ----
__device__ int            g_cnt[NN];
__device__ int            g_beg[NN];
__device__ int            g_total;
__device__ float          g_dinv[NN];
__device__ unsigned short g_rank[NE];     // rank of edge within its target bucket
__device__ int2           g_edge[NE];     // {src, wgt-as-int} packed
__device__ uint2          g_curh[9][NF4]; // fp16 cur chain: slot 0 = x, 1..8 per-layer
__device__ float4         g_h[NF4];       // blended h = c*u + (1-c)*x (fp32 for GEMM)
__device__ float          g_tk[8];
__device__ float          g_cst[1];

static __device__ __forceinline__ uint2 pack4h(float a, float b, float c, float d) {
    __half2 lo = __floats2half2_rn(a, b);
    __half2 hi = __floats2half2_rn(c, d);
    uint2 r;
    r.x = *reinterpret_cast<unsigned*>(&lo);
    r.y = *reinterpret_cast<unsigned*>(&hi);
    return r;
}

static __device__ __forceinline__ float4 unpack4h(uint2 p) {
    float2 lo = __half22float2(*reinterpret_cast<__half2*>(&p.x));
    float2 hi = __half22float2(*reinterpret_cast<__half2*>(&p.y));
    return make_float4(lo.x, lo.y, hi.x, hi.y);
}

// ---- init: slot0 = fp16(x), counters = 0 ----
__global__ void k_init(const float4* __restrict__ x4) {
    int i = blockIdx.x * blockDim.x + threadIdx.x;
    if (i < NF4) {
        float4 v = x4[i];
        g_curh[0][i] = pack4h(v.x, v.y, v.z, v.w);
    }
    if (i < NN) g_cnt[i] = 0;
    if (i == 0) g_total = 0;
}

// ---- count + rank: atomic return value IS the within-bucket rank ----
__global__ void k_count(const int* __restrict__ ei) {
    int e = blockIdx.x * blockDim.x + threadIdx.x;
    if (e < NE) {
        int rank = atomicAdd(&g_cnt[ei[NE + e]], 1);
        g_rank[e] = (unsigned short)rank;
    }
}

// ---- dinv = deg^-1/2 (0 -> 1); bucket allocation; scalar prep ----
__global__ void k_dinv(const float* __restrict__ kv, const float* __restrict__ wt) {
    int n = blockIdx.x * blockDim.x + threadIdx.x;
    if (n < NN) {
        int c = g_cnt[n];
        g_dinv[n] = rsqrtf((float)(c ? c : 1));
        g_beg[n] = atomicAdd(&g_total, c);
    }
    if (n < 8)  g_tk[n] = tanhf(kv[n]);
    if (n == 8) g_cst[0] = 1.f / (1.f + expf(-wt[0]));
}

// ---- fill buckets: ATOMIC-FREE (beg + precomputed rank) ----
__global__ void k_fill(const int* __restrict__ ei) {
    int e = blockIdx.x * blockDim.x + threadIdx.x;
    if (e < NE) {
        int r = ei[e];
        int c = ei[NE + e];
        int pos = g_beg[c] + (int)g_rank[e];
        float w = g_dinv[r] * g_dinv[c];
        g_edge[pos] = make_int2(r, __float_as_int(w));
    }
}

// ---- one propagation layer: warp-per-node, all-fp16 storage, fp32 math ----
__global__ void __launch_bounds__(256) k_layer(int s) {
    int gw   = (blockIdx.x * blockDim.x + threadIdx.x) >> 5;
    int lane = threadIdx.x & 31;
    if (gw >= NN) return;
    const uint2* __restrict__ hin  = g_curh[s];
    uint2* __restrict__       hout = g_curh[s + 1];

    int beg = g_beg[gw];
    int end = beg + g_cnt[gw];
    float ax = 0.f, ay = 0.f, az = 0.f, aw = 0.f;

    int e = beg;
    for (; e + 7 < end; e += 8) {
        int2 e0 = g_edge[e + 0], e1 = g_edge[e + 1], e2 = g_edge[e + 2], e3 = g_edge[e + 3];
        int2 e4 = g_edge[e + 4], e5 = g_edge[e + 5], e6 = g_edge[e + 6], e7 = g_edge[e + 7];
        uint2 p0 = hin[e0.x * 32 + lane];
        uint2 p1 = hin[e1.x * 32 + lane];
        uint2 p2 = hin[e2.x * 32 + lane];
        uint2 p3 = hin[e3.x * 32 + lane];
        uint2 p4 = hin[e4.x * 32 + lane];
        uint2 p5 = hin[e5.x * 32 + lane];
        uint2 p6 = hin[e6.x * 32 + lane];
        uint2 p7 = hin[e7.x * 32 + lane];
#define ACC(P, EV) do {                                                   \
        float w = __int_as_float((EV).y);                                 \
        float2 lo = __half22float2(*reinterpret_cast<__half2*>(&(P).x));  \
        float2 hi = __half22float2(*reinterpret_cast<__half2*>(&(P).y));  \
        ax = fmaf(w, lo.x, ax); ay = fmaf(w, lo.y, ay);                   \
        az = fmaf(w, hi.x, az); aw = fmaf(w, hi.y, aw); } while (0)
        ACC(p0, e0); ACC(p1, e1); ACC(p2, e2); ACC(p3, e3);
        ACC(p4, e4); ACC(p5, e5); ACC(p6, e6); ACC(p7, e7);
    }
    for (; e + 3 < end; e += 4) {
        int2 e0 = g_edge[e + 0], e1 = g_edge[e + 1], e2 = g_edge[e + 2], e3 = g_edge[e + 3];
        uint2 p0 = hin[e0.x * 32 + lane];
        uint2 p1 = hin[e1.x * 32 + lane];
        uint2 p2 = hin[e2.x * 32 + lane];
        uint2 p3 = hin[e3.x * 32 + lane];
        ACC(p0, e0); ACC(p1, e1); ACC(p2, e2); ACC(p3, e3);
    }
    for (; e < end; e++) {
        int2 ev = g_edge[e];
        uint2 p = hin[ev.x * 32 + lane];
        ACC(p, ev);
    }
#undef ACC

    int off = gw * 32 + lane;
    float4 cv = unpack4h(hin[off]);   // fp16 carry, fp32 math
    hout[off] = pack4h(cv.x - ax, cv.y - ay, cv.z - az, cv.w - aw);
}

// ---- blend: h = c * sum tk_i*cur_{i+1} + (1-c)*x  (fp16 reads, fp32 out) ----
__global__ void __launch_bounds__(256) k_blend(const float4* __restrict__ x4) {
    int i = blockIdx.x * blockDim.x + threadIdx.x;
    if (i >= NF4) return;
    float c = g_cst[0], d = 1.f - c;
    float ux = 0.f, uy = 0.f, uz = 0.f, uw = 0.f;
#pragma unroll
    for (int s = 0; s < 8; s++) {
        float tk = g_tk[s];
        float4 cv = unpack4h(g_curh[s + 1][i]);
        ux = fmaf(tk, cv.x, ux); uy = fmaf(tk, cv.y, uy);
        uz = fmaf(tk, cv.z, uz); uw = fmaf(tk, cv.w, uw);
    }
    float4 xv = x4[i];
    g_h[i] = make_float4(c * ux + d * xv.x, c * uy + d * xv.y,
                         c * uz + d * xv.z, c * uw + d * xv.w);
}

// ---- epilogue: pure GEMM out = relu(h @ W^T + b) ----
// BM=64, BN=64 (grid.y=2), BK=32, 4x4 register tile (R9-proven schedule).
__global__ void __launch_bounds__(256) k_out(const float4* __restrict__ W4,
                                             const float*  __restrict__ bias,
                                             float*        __restrict__ out) {
    __shared__ float sA[32][68];
    __shared__ float sB[32][68];
    int mblk = blockIdx.x * 64;
    int nblk = blockIdx.y * 64;
    int tid = threadIdx.x;
    int tx = tid & 15, ty = tid >> 4;

    float acc[4][4];
#pragma unroll
    for (int i = 0; i < 4; i++)
#pragma unroll
        for (int j = 0; j < 4; j++) acc[i][j] = 0.f;

    for (int k0 = 0; k0 < 128; k0 += 32) {
#pragma unroll
        for (int l = 0; l < 2; l++) {
            int idx = tid + l * 256;
            int m  = idx >> 3;
            int kq = idx & 7;
            int kk = kq * 4;
            int node = mblk + m;
            float4 hv = make_float4(0.f, 0.f, 0.f, 0.f);
            if (node < NN) hv = g_h[node * 32 + (k0 >> 2) + kq];
            sA[kk + 0][m] = hv.x;
            sA[kk + 1][m] = hv.y;
            sA[kk + 2][m] = hv.z;
            sA[kk + 3][m] = hv.w;
            float4 wv = W4[(nblk + m) * 32 + (k0 >> 2) + kq];
            sB[kk + 0][m] = wv.x;
            sB[kk + 1][m] = wv.y;
            sB[kk + 2][m] = wv.z;
            sB[kk + 3][m] = wv.w;
        }
        __syncthreads();
#pragma unroll
        for (int kk = 0; kk < 32; kk++) {
            float a[4], bb[4];
#pragma unroll
            for (int i = 0; i < 4; i++) a[i] = sA[kk][ty * 4 + i];
#pragma unroll
            for (int j = 0; j < 4; j++) bb[j] = sB[kk][tx * 4 + j];
#pragma unroll
            for (int i = 0; i < 4; i++)
#pragma unroll
                for (int j = 0; j < 4; j++)
                    acc[i][j] = fmaf(a[i], bb[j], acc[i][j]);
        }
        __syncthreads();
    }

#pragma unroll
    for (int i = 0; i < 4; i++) {
        int node = mblk + ty * 4 + i;
        if (node >= NN) continue;
#pragma unroll
        for (int j = 0; j < 4; j++) {
            int jj = nblk + tx * 4 + j;
            float v = acc[i][j] + bias[jj];
            out[node * 128 + jj] = v > 0.f ? v : 0.f;
        }
    }
}

extern "C" void kernel_launch(void* const* d_in, const int* in_sizes, int n_in,
                              void* d_out, int out_size) {
    const float4* x4   = (const float4*)d_in[0];
    const int*    ei   = (const int*)d_in[1];
    const float*  kv   = (const float*)d_in[2];
    const float*  wt   = (const float*)d_in[3];
    const float4* W4   = (const float4*)d_in[4];
    const float*  bias = (const float*)d_in[5];
    float*        out  = (float*)d_out;

    k_init<<<(NF4 + 255) / 256, 256>>>(x4);
    k_count<<<(NE + 255) / 256, 256>>>(ei);
    k_dinv<<<(NN + 255) / 256, 256>>>(kv, wt);
    k_fill<<<(NE + 255) / 256, 256>>>(ei);

    for (int l = 0; l < 8; l++)
        k_layer<<<(NN * 32 + 255) / 256, 256>>>(l);

    k_blend<<<(NF4 + 255) / 256, 256>>>(x4);

    dim3 g((NN + 63) / 64, 2);
    k_out<<<g, 256>>>(W4, bias, out);
}